// round 11
// baseline (speedup 1.0000x reference)
#include <cuda_runtime.h>
#include <cuda_fp16.h>
#include <cstdint>

#define D_MODEL 768
#define N_LAT   16384
#define NROWS   8192
#define TOPK    32
#define NCAND   48
#define CAP     64
#define NCHUNKS 4
#define ROWS_PER_CHUNK (NROWS / NCHUNKS)   // 2048

// ---------------- device scratch (no allocs allowed) ----------------
__device__ int   g_sel_idx[NROWS * TOPK];
__device__ float g_sel_val[NROWS * TOPK];
__device__ int   g_cand[NROWS * CAP];
__device__ int   g_nhi[NROWS];
__device__ int   g_neq[NROWS];
__device__ float g_Wt[(size_t)N_LAT * D_MODEL];           // W_dec transposed
__device__ __half g_x1[(size_t)NROWS * D_MODEL];          // fp16(x)
__device__ __half g_w1[(size_t)N_LAT * D_MODEL];          // fp16(W_enc)

// ---------------- streams/events for pipelined graph (static init,
// before the harness's memory checkpoints; no device allocs here) ----
static cudaStream_t g_s1;
static cudaEvent_t  g_evStart, g_evG[NCHUNKS], g_evEnd;
namespace {
struct InitStreams {
    InitStreams() {
        cudaStreamCreateWithFlags(&g_s1, cudaStreamNonBlocking);
        cudaEventCreateWithFlags(&g_evStart, cudaEventDisableTiming);
        for (int i = 0; i < NCHUNKS; ++i)
            cudaEventCreateWithFlags(&g_evG[i], cudaEventDisableTiming);
        cudaEventCreateWithFlags(&g_evEnd, cudaEventDisableTiming);
    }
};
static InitStreams g_init_streams;
}

__device__ __forceinline__ uint32_t smem_u32(const void* p) {
    uint32_t a;
    asm("{ .reg .u64 t; cvta.to.shared.u64 t, %1; cvt.u32.u64 %0, t; }" : "=r"(a) : "l"(p));
    return a;
}

// =====================================================================
// convert kernels
// =====================================================================
__global__ __launch_bounds__(256) void convert_x(const float* __restrict__ x)
{
    int i = blockIdx.x * 256 + threadIdx.x;
    float4 v = ((const float4*)x)[i];
    __half2 a = __halves2half2(__float2half_rn(v.x), __float2half_rn(v.y));
    __half2 b = __halves2half2(__float2half_rn(v.z), __float2half_rn(v.w));
    ((uint2*)g_x1)[i] = make_uint2(*(uint32_t*)&a, *(uint32_t*)&b);
}

__global__ __launch_bounds__(256) void convert_w(const float* __restrict__ W)
{
    int i = blockIdx.x * 256 + threadIdx.x;
    float4 v = ((const float4*)W)[i];
    __half2 a = __halves2half2(__float2half_rn(v.x), __float2half_rn(v.y));
    __half2 b = __halves2half2(__float2half_rn(v.z), __float2half_rn(v.w));
    ((uint2*)g_w1)[i] = make_uint2(*(uint32_t*)&a, *(uint32_t*)&b);
}

// =====================================================================
// GEMM1: pre = x @ W_enc^T + b_enc, fp16 MMA, fp32 accum (round-6 config:
// CTA 128x128, BK=64, 8 warps warp-64x32, 2-stage cp.async, 2 CTAs/SM)
// =====================================================================
#define GBK 64
#define ROWB 144
#define TILEB (128 * ROWB)             // 18432
#define STAGEB (2 * TILEB)             // A B
#define GSTAGES 2
#define GEMM_SMEM (GSTAGES * STAGEB)   // 73728

__device__ __forceinline__ void ldsm4(uint32_t& r0, uint32_t& r1, uint32_t& r2, uint32_t& r3,
                                      uint32_t addr) {
    asm volatile("ldmatrix.sync.aligned.m8n8.x4.shared.b16 {%0,%1,%2,%3}, [%4];"
                 : "=r"(r0), "=r"(r1), "=r"(r2), "=r"(r3) : "r"(addr));
}
__device__ __forceinline__ void mma16816(float* c, const uint32_t* a, const uint32_t* b) {
    asm volatile("mma.sync.aligned.m16n8k16.row.col.f32.f16.f16.f32 "
                 "{%0,%1,%2,%3}, {%4,%5,%6,%7}, {%8,%9}, {%0,%1,%2,%3};"
                 : "+f"(c[0]), "+f"(c[1]), "+f"(c[2]), "+f"(c[3])
                 : "r"(a[0]), "r"(a[1]), "r"(a[2]), "r"(a[3]), "r"(b[0]), "r"(b[1]));
}
__device__ __forceinline__ void cpasync16(uint32_t dst, const void* src) {
    asm volatile("cp.async.cg.shared.global [%0], [%1], 16;" :: "r"(dst), "l"(src));
}

__global__ __launch_bounds__(256, 2) void gemm_mma(
    const float* __restrict__ bias, float* __restrict__ C, int bm0)
{
    extern __shared__ char sm[];
    const uint32_t sb = smem_u32(sm);
    const int tid = threadIdx.x;
    const int bm = bm0 + blockIdx.y * 128;
    const int bn = blockIdx.x * 128;
    const int lane = tid & 31;
    const int warp = tid >> 5;
    const int wm = warp & 1;
    const int wn = warp >> 1;

    float acc[4][4][4];
#pragma unroll
    for (int i = 0; i < 4; i++)
#pragma unroll
        for (int j = 0; j < 4; j++)
#pragma unroll
            for (int q = 0; q < 4; q++) acc[i][j][q] = 0.f;

    const __half* ax = g_x1 + (size_t)bm * D_MODEL;
    const __half* bw = g_w1 + (size_t)bn * D_MODEL;

    auto load_stage = [&](int s, int c) {
        const int k0 = c * GBK;
#pragma unroll
        for (int i = 0; i < 8; ++i) {
            int idx = tid + i * 256;
            int t = idx >> 10;
            int rem = idx & 1023;
            int row = rem >> 3, ch = rem & 7;
            uint32_t dst = sb + s * STAGEB + t * TILEB + row * ROWB + ch * 16;
            const __half* base = (t == 0) ? ax : bw;
            cpasync16(dst, base + (size_t)row * D_MODEL + k0 + ch * 8);
        }
    };

    const int NCH = D_MODEL / GBK;   // 12
    load_stage(0, 0);
    asm volatile("cp.async.commit_group;");
    load_stage(1, 1);
    asm volatile("cp.async.commit_group;");

    const uint32_t a_row = (uint32_t)(wm * 64 + (lane & 7) + ((lane >> 3) & 1) * 8);
    const uint32_t a_off = a_row * ROWB + ((lane >> 4) * 16);
    const uint32_t b_row = (uint32_t)(wn * 32 + (lane & 7) + ((lane >> 4) & 1) * 8);
    const uint32_t b_off = b_row * ROWB + (((lane >> 3) & 1) * 16);

    for (int c = 0; c < NCH; ++c) {
        asm volatile("cp.async.wait_group %0;" :: "n"(1));
        __syncthreads();

        const uint32_t stg = sb + (c & 1) * STAGEB;
#pragma unroll
        for (int kg = 0; kg < 4; ++kg) {
            const uint32_t kgo = kg * 32;
            uint32_t af[4][4], bf[4][2];
#pragma unroll
            for (int q = 0; q < 2; ++q)
                ldsm4(bf[2 * q][0], bf[2 * q][1], bf[2 * q + 1][0], bf[2 * q + 1][1],
                      stg + 1 * TILEB + b_off + q * 16 * ROWB + kgo);
#pragma unroll
            for (int mt = 0; mt < 4; ++mt)
                ldsm4(af[mt][0], af[mt][1], af[mt][2], af[mt][3],
                      stg + 0 * TILEB + a_off + mt * 16 * ROWB + kgo);
#pragma unroll
            for (int mt = 0; mt < 4; ++mt)
#pragma unroll
                for (int nt = 0; nt < 4; ++nt) mma16816(acc[mt][nt], af[mt], bf[nt]);
        }
        __syncthreads();
        if (c + 2 < NCH) load_stage(c & 1, c + 2);
        asm volatile("cp.async.commit_group;");
    }

#pragma unroll
    for (int nt = 0; nt < 4; ++nt) {
        const int col = bn + wn * 32 + nt * 8 + (lane & 3) * 2;
        const float2 bv = *(const float2*)&bias[col];
#pragma unroll
        for (int mt = 0; mt < 4; ++mt) {
            const int row = bm + wm * 64 + mt * 16 + (lane >> 2);
            float2 v0 = make_float2(acc[mt][nt][0] + bv.x, acc[mt][nt][1] + bv.y);
            float2 v1 = make_float2(acc[mt][nt][2] + bv.x, acc[mt][nt][3] + bv.y);
            *(float2*)&C[(size_t)row * N_LAT + col] = v0;
            *(float2*)&C[(size_t)(row + 8) * N_LAT + col] = v1;
        }
    }
}

// =====================================================================
// topk: candidate superset via 2-level radix bins + fused latents zeroing
// =====================================================================
__global__ __launch_bounds__(512) void topk_kernel(const float* __restrict__ pre,
                                                   float* __restrict__ latents,
                                                   int row0)
{
    extern __shared__ unsigned su[];           // 16384 keys
    __shared__ unsigned hist[2048];
    __shared__ int csum[512];
    __shared__ int s_t1, s_cab, s_b, s_c, s_target;
    __shared__ int s_nhi, s_neq;

    const int row = row0 + blockIdx.x;
    const int tid = threadIdx.x;
    const float* prow = pre + (size_t)row * N_LAT;
    float* lrow = latents + (size_t)row * N_LAT;

    for (int i = tid; i < 2048; i += 512) hist[i] = 0u;
    if (tid == 0) { s_nhi = 0; s_neq = 0; s_target = NCAND; }
    __syncthreads();

    const float4 z4 = make_float4(0.f, 0.f, 0.f, 0.f);
    for (int i = tid; i < N_LAT / 4; i += 512) {
        float4 v = ((const float4*)prow)[i];
        ((float4*)lrow)[i] = z4;
        unsigned b0 = __float_as_uint(v.x), b1 = __float_as_uint(v.y);
        unsigned b2 = __float_as_uint(v.z), b3 = __float_as_uint(v.w);
        unsigned u0 = (b0 & 0x80000000u) ? ~b0 : (b0 | 0x80000000u);
        unsigned u1 = (b1 & 0x80000000u) ? ~b1 : (b1 | 0x80000000u);
        unsigned u2 = (b2 & 0x80000000u) ? ~b2 : (b2 | 0x80000000u);
        unsigned u3 = (b3 & 0x80000000u) ? ~b3 : (b3 | 0x80000000u);
        *(uint4*)&su[i * 4] = make_uint4(u0, u1, u2, u3);
        atomicAdd(&hist[u0 >> 21], 1u);
        atomicAdd(&hist[u1 >> 21], 1u);
        atomicAdd(&hist[u2 >> 21], 1u);
        atomicAdd(&hist[u3 >> 21], 1u);
    }

    unsigned P = 0;
#pragma unroll
    for (int pass = 0; pass < 2; ++pass) {
        __syncthreads();
        const int target = s_target;
        int cs = (int)hist[tid * 4] + (int)hist[tid * 4 + 1]
               + (int)hist[tid * 4 + 2] + (int)hist[tid * 4 + 3];
        csum[tid] = cs;
        __syncthreads();
#pragma unroll
        for (int off = 1; off < 512; off <<= 1) {
            int v = csum[tid] + ((tid + off < 512) ? csum[tid + off] : 0);
            __syncthreads();
            csum[tid] = v;
            __syncthreads();
        }
        int nxt = (tid + 1 < 512) ? csum[tid + 1] : 0;
        if (csum[tid] >= target && nxt < target) { s_t1 = tid; s_cab = nxt; }
        __syncthreads();
        if (tid == 0) {
            int t1 = s_t1, cum = s_cab, b = 0, c = 0;
            for (int bb = t1 * 4 + 3;; --bb) {
                if (cum + (int)hist[bb] >= target) { b = bb; c = cum; break; }
                cum += (int)hist[bb];
            }
            s_b = b; s_c = c;
        }
        __syncthreads();
        if (pass == 0) {
            const int b1 = s_b;
            const int c1 = s_c;
            if (tid == 0) s_target = NCAND - c1;
            __syncthreads();
            for (int i = tid; i < 2048; i += 512) hist[i] = 0u;
            __syncthreads();
            for (int i = tid; i < N_LAT; i += 512) {
                unsigned u = su[i];
                if ((int)(u >> 21) == b1) atomicAdd(&hist[(u >> 10) & 2047u], 1u);
            }
            P = (unsigned)b1 << 11;
        }
    }
    P |= (unsigned)s_b;
    __syncthreads();

    for (int i = tid; i < N_LAT; i += 512) {
        unsigned hi = su[i] >> 10;
        if (hi > P) {
            int p = atomicAdd(&s_nhi, 1);
            if (p < CAP) g_cand[row * CAP + p] = i;
        } else if (hi == P) {
            int p = atomicAdd(&s_neq, 1);
            if (p < CAP) g_cand[row * CAP + (CAP - 1 - p)] = i;
        }
    }
    __syncthreads();
    if (tid == 0) {
        g_nhi[row] = s_nhi < CAP ? s_nhi : CAP;
        g_neq[row] = s_neq < CAP ? s_neq : CAP;
    }
}

// =====================================================================
// refine: compensated-fp32 exact dots for <=CAP candidates, top-32 select
// =====================================================================
__global__ __launch_bounds__(256) void refine_kernel(
    const float* __restrict__ x, const float* __restrict__ We,
    const float* __restrict__ be, float* __restrict__ latents, int row0)
{
    __shared__ float4 xs4[D_MODEL / 4];
    __shared__ float cv[CAP];
    __shared__ int   ci[CAP];
    const int row = row0 + blockIdx.x;
    const int tid = threadIdx.x;
    const int lane = tid & 31, warp = tid >> 5;

    for (int j = tid; j < D_MODEL / 4; j += 256)
        xs4[j] = ((const float4*)(x + (size_t)row * D_MODEL))[j];
    if (tid < CAP) {
        int nhi = g_nhi[row], neq = g_neq[row];
        bool valid = (tid < nhi) || (tid >= CAP - neq);
        ci[tid] = valid ? g_cand[row * CAP + tid] : -1;
        cv[tid] = -1e30f;
    }
    __syncthreads();

    for (int c = warp; c < CAP; c += 8) {
        const int idx = ci[c];
        if (idx < 0) continue;
        const float4* wr = (const float4*)(We + (size_t)idx * D_MODEL);
        float s = 0.f, e = 0.f;
#pragma unroll
        for (int it = 0; it < D_MODEL / 128; ++it) {   // 6
            float4 w = wr[lane + it * 32];
            float4 a = xs4[lane + it * 32];
            float av[4] = {a.x, a.y, a.z, a.w};
            float wv[4] = {w.x, w.y, w.z, w.w};
#pragma unroll
            for (int q = 0; q < 4; ++q) {
                float p = av[q] * wv[q];
                float pe = fmaf(av[q], wv[q], -p);
                float t = s + p;
                float z = t - s;
                e += ((s - (t - z)) + (p - z)) + pe;
                s = t;
            }
        }
#pragma unroll
        for (int o = 16; o > 0; o >>= 1) {
            float so = __shfl_down_sync(0xffffffffu, s, o);
            float eo = __shfl_down_sync(0xffffffffu, e, o);
            float t = s + so;
            float z = t - s;
            e += ((s - (t - z)) + (so - z)) + eo;
            s = t;
        }
        if (lane == 0) {
            float bb = be[idx];
            float t = s + bb;
            float z = t - s;
            e += (s - (t - z)) + (bb - z);
            cv[c] = t + e;
        }
    }
    __syncthreads();

    if (tid < CAP) {
        const int idx = ci[tid];
        if (idx >= 0) {
            const float v = cv[tid];
            int r = 0;
#pragma unroll
            for (int j = 0; j < CAP; ++j) {
                float u = cv[j];
                r += (u > v) || (u == v && ci[j] < idx && ci[j] >= 0);
            }
            if (r < TOPK) {
                float rv = v > 0.f ? v : 0.f;
                latents[(size_t)row * N_LAT + idx] = rv;
                g_sel_idx[row * TOPK + r] = idx;
                g_sel_val[row * TOPK + r] = rv;
            }
        }
    }
}

// ---------------- W_dec transpose ----------------
__global__ void transpose_kernel(const float* __restrict__ W)
{
    __shared__ float t[32][33];
    const int j0 = blockIdx.x * 32;
    const int d0 = blockIdx.y * 32;
    const int tx = threadIdx.x;
    const int ty0 = threadIdx.y;
#pragma unroll
    for (int s = 0; s < 32; s += 8) {
        int ty = ty0 + s;
        t[ty][tx] = W[(size_t)(d0 + ty) * N_LAT + j0 + tx];
    }
    __syncthreads();
#pragma unroll
    for (int s = 0; s < 32; s += 8) {
        int ty = ty0 + s;
        g_Wt[(size_t)(j0 + ty) * D_MODEL + d0 + tx] = t[tx][ty];
    }
}

// ---------------- sparse decode ----------------
__global__ __launch_bounds__(256) void recon_kernel(
    const float* __restrict__ b_dec, float* __restrict__ recon)
{
    __shared__ int sidx[TOPK];
    __shared__ float sval[TOPK];
    const int row = blockIdx.x;
    const int tid = threadIdx.x;
    if (tid < TOPK) {
        sidx[tid] = g_sel_idx[row * TOPK + tid];
        sval[tid] = g_sel_val[row * TOPK + tid];
    }
    __syncthreads();
    float a0 = 0.f, a1 = 0.f, a2 = 0.f;
#pragma unroll 4
    for (int k = 0; k < TOPK; k++) {
        float v = sval[k];
        const float* w = &g_Wt[(size_t)sidx[k] * D_MODEL];
        a0 += v * w[tid];
        a1 += v * w[tid + 256];
        a2 += v * w[tid + 512];
    }
    const size_t o = (size_t)row * D_MODEL;
    recon[o + tid]       = a0 + b_dec[tid];
    recon[o + tid + 256] = a1 + b_dec[tid + 256];
    recon[o + tid + 512] = a2 + b_dec[tid + 512];
}

// ---------------- launch: 4-chunk pipelined fork/join graph ----------------
extern "C" void kernel_launch(void* const* d_in, const int* in_sizes, int n_in,
                              void* d_out, int out_size)
{
    const float* x  = (const float*)d_in[0];
    const float* We = (const float*)d_in[1];
    const float* be = (const float*)d_in[2];
    const float* Wd = (const float*)d_in[3];
    const float* bd = (const float*)d_in[4];

    float* out     = (float*)d_out;
    float* latents = out;
    float* recon   = out + (size_t)NROWS * N_LAT;
    float* pre     = recon + (size_t)NROWS * D_MODEL;

    cudaFuncSetAttribute(gemm_mma, cudaFuncAttributeMaxDynamicSharedMemorySize, GEMM_SMEM);
    cudaFuncSetAttribute(topk_kernel, cudaFuncAttributeMaxDynamicSharedMemorySize,
                         N_LAT * (int)sizeof(unsigned));

    // fork s1 from the origin stream
    cudaEventRecord(g_evStart, 0);
    cudaStreamWaitEvent(g_s1, g_evStart, 0);

    // s1: transpose (only needed by recon at the end)
    transpose_kernel<<<dim3(N_LAT / 32, D_MODEL / 32), dim3(32, 8), 0, g_s1>>>(Wd);

    // s0: converts feed the GEMM
    convert_x<<<NROWS * D_MODEL / 4 / 256, 256>>>(x);
    convert_w<<<N_LAT * D_MODEL / 4 / 256, 256>>>(We);

    for (int c = 0; c < NCHUNKS; ++c) {
        const int row0 = c * ROWS_PER_CHUNK;
        // s0: GEMM chunk
        gemm_mma<<<dim3(N_LAT / 128, ROWS_PER_CHUNK / 128), 256, GEMM_SMEM>>>(
            be, pre, row0);
        cudaEventRecord(g_evG[c], 0);
        // s1: selection pipeline for this chunk (overlaps next GEMM chunk)
        cudaStreamWaitEvent(g_s1, g_evG[c], 0);
        topk_kernel<<<ROWS_PER_CHUNK, 512, N_LAT * sizeof(unsigned), g_s1>>>(
            pre, latents, row0);
        refine_kernel<<<ROWS_PER_CHUNK, 256, 0, g_s1>>>(x, We, be, latents, row0);
    }

    // s1: decode (needs transpose + all refines; both ordered on s1)
    recon_kernel<<<NROWS, 256, 0, g_s1>>>(bd, recon);

    // join s1 back into the origin stream
    cudaEventRecord(g_evEnd, g_s1);
    cudaStreamWaitEvent(0, g_evEnd, 0);
}

// round 12
// speedup vs baseline: 1.0870x; 1.0870x over previous
#include <cuda_runtime.h>
#include <cuda_fp16.h>
#include <cstdint>

#define D_MODEL 768
#define N_LAT   16384
#define NROWS   8192
#define TOPK    32
#define NCAND   48
#define CAP     64

// ---------------- device scratch (no allocs allowed) ----------------
__device__ int   g_cand[NROWS * CAP];
__device__ int   g_nhi[NROWS];
__device__ int   g_neq[NROWS];
__device__ float g_Wt[(size_t)N_LAT * D_MODEL];           // W_dec transposed
__device__ __half g_x1[(size_t)NROWS * D_MODEL];          // fp16(x)
__device__ __half g_w1[(size_t)N_LAT * D_MODEL];          // fp16(W_enc)

__device__ __forceinline__ uint32_t smem_u32(const void* p) {
    uint32_t a;
    asm("{ .reg .u64 t; cvta.to.shared.u64 t, %1; cvt.u32.u64 %0, t; }" : "=r"(a) : "l"(p));
    return a;
}

// =====================================================================
// prep: convert x->fp16, W_enc->fp16, transpose W_dec (single launch)
// =====================================================================
#define GRID_CX (NROWS * D_MODEL / 4 / 256)            // 6144
#define GRID_CW (N_LAT * D_MODEL / 4 / 256)            // 49152
#define GRID_TR ((N_LAT / 32) * (D_MODEL / 32))        // 12288

__global__ __launch_bounds__(256) void prep_kernel(
    const float* __restrict__ x, const float* __restrict__ We,
    const float* __restrict__ Wd)
{
    __shared__ float t[32][33];
    const int b = blockIdx.x;
    const int tid = threadIdx.x;

    if (b < GRID_CX) {
        int i = b * 256 + tid;
        float4 v = ((const float4*)x)[i];
        __half2 a = __halves2half2(__float2half_rn(v.x), __float2half_rn(v.y));
        __half2 c = __halves2half2(__float2half_rn(v.z), __float2half_rn(v.w));
        ((uint2*)g_x1)[i] = make_uint2(*(uint32_t*)&a, *(uint32_t*)&c);
    } else if (b < GRID_CX + GRID_CW) {
        int i = (b - GRID_CX) * 256 + tid;
        float4 v = ((const float4*)We)[i];
        __half2 a = __halves2half2(__float2half_rn(v.x), __float2half_rn(v.y));
        __half2 c = __halves2half2(__float2half_rn(v.z), __float2half_rn(v.w));
        ((uint2*)g_w1)[i] = make_uint2(*(uint32_t*)&a, *(uint32_t*)&c);
    } else {
        int tb = b - GRID_CX - GRID_CW;
        const int j0 = (tb & 511) * 32;        // N_LAT/32 = 512
        const int d0 = (tb >> 9) * 32;
        const int tx = tid & 31;
        const int ty0 = tid >> 5;
#pragma unroll
        for (int s = 0; s < 32; s += 8) {
            int ty = ty0 + s;
            t[ty][tx] = Wd[(size_t)(d0 + ty) * N_LAT + j0 + tx];
        }
        __syncthreads();
#pragma unroll
        for (int s = 0; s < 32; s += 8) {
            int ty = ty0 + s;
            g_Wt[(size_t)(j0 + ty) * D_MODEL + d0 + tx] = t[tx][ty];
        }
    }
}

// =====================================================================
// GEMM1: pre = x @ W_enc^T + b_enc, fp16 MMA, fp32 accum (round-6 best:
// CTA 128x128, BK=64, 8 warps warp-64x32, 2-stage cp.async, 2 CTAs/SM)
// =====================================================================
#define GBK 64
#define ROWB 144
#define TILEB (128 * ROWB)             // 18432
#define STAGEB (2 * TILEB)             // A B
#define GSTAGES 2
#define GEMM_SMEM (GSTAGES * STAGEB)   // 73728

__device__ __forceinline__ void ldsm4(uint32_t& r0, uint32_t& r1, uint32_t& r2, uint32_t& r3,
                                      uint32_t addr) {
    asm volatile("ldmatrix.sync.aligned.m8n8.x4.shared.b16 {%0,%1,%2,%3}, [%4];"
                 : "=r"(r0), "=r"(r1), "=r"(r2), "=r"(r3) : "r"(addr));
}
__device__ __forceinline__ void mma16816(float* c, const uint32_t* a, const uint32_t* b) {
    asm volatile("mma.sync.aligned.m16n8k16.row.col.f32.f16.f16.f32 "
                 "{%0,%1,%2,%3}, {%4,%5,%6,%7}, {%8,%9}, {%0,%1,%2,%3};"
                 : "+f"(c[0]), "+f"(c[1]), "+f"(c[2]), "+f"(c[3])
                 : "r"(a[0]), "r"(a[1]), "r"(a[2]), "r"(a[3]), "r"(b[0]), "r"(b[1]));
}
__device__ __forceinline__ void cpasync16(uint32_t dst, const void* src) {
    asm volatile("cp.async.cg.shared.global [%0], [%1], 16;" :: "r"(dst), "l"(src));
}

__global__ __launch_bounds__(256, 2) void gemm_mma(
    const float* __restrict__ bias, float* __restrict__ C)
{
    extern __shared__ char sm[];
    const uint32_t sb = smem_u32(sm);
    const int tid = threadIdx.x;
    const int bm = blockIdx.y * 128;
    const int bn = blockIdx.x * 128;
    const int lane = tid & 31;
    const int warp = tid >> 5;
    const int wm = warp & 1;
    const int wn = warp >> 1;

    float acc[4][4][4];
#pragma unroll
    for (int i = 0; i < 4; i++)
#pragma unroll
        for (int j = 0; j < 4; j++)
#pragma unroll
            for (int q = 0; q < 4; q++) acc[i][j][q] = 0.f;

    const __half* ax = g_x1 + (size_t)bm * D_MODEL;
    const __half* bw = g_w1 + (size_t)bn * D_MODEL;

    auto load_stage = [&](int s, int c) {
        const int k0 = c * GBK;
#pragma unroll
        for (int i = 0; i < 8; ++i) {
            int idx = tid + i * 256;
            int t = idx >> 10;
            int rem = idx & 1023;
            int row = rem >> 3, ch = rem & 7;
            uint32_t dst = sb + s * STAGEB + t * TILEB + row * ROWB + ch * 16;
            const __half* base = (t == 0) ? ax : bw;
            cpasync16(dst, base + (size_t)row * D_MODEL + k0 + ch * 8);
        }
    };

    const int NCH = D_MODEL / GBK;   // 12
    load_stage(0, 0);
    asm volatile("cp.async.commit_group;");
    load_stage(1, 1);
    asm volatile("cp.async.commit_group;");

    const uint32_t a_row = (uint32_t)(wm * 64 + (lane & 7) + ((lane >> 3) & 1) * 8);
    const uint32_t a_off = a_row * ROWB + ((lane >> 4) * 16);
    const uint32_t b_row = (uint32_t)(wn * 32 + (lane & 7) + ((lane >> 4) & 1) * 8);
    const uint32_t b_off = b_row * ROWB + (((lane >> 3) & 1) * 16);

    for (int c = 0; c < NCH; ++c) {
        asm volatile("cp.async.wait_group %0;" :: "n"(1));
        __syncthreads();

        const uint32_t stg = sb + (c & 1) * STAGEB;
#pragma unroll
        for (int kg = 0; kg < 4; ++kg) {
            const uint32_t kgo = kg * 32;
            uint32_t af[4][4], bf[4][2];
#pragma unroll
            for (int q = 0; q < 2; ++q)
                ldsm4(bf[2 * q][0], bf[2 * q][1], bf[2 * q + 1][0], bf[2 * q + 1][1],
                      stg + 1 * TILEB + b_off + q * 16 * ROWB + kgo);
#pragma unroll
            for (int mt = 0; mt < 4; ++mt)
                ldsm4(af[mt][0], af[mt][1], af[mt][2], af[mt][3],
                      stg + 0 * TILEB + a_off + mt * 16 * ROWB + kgo);
#pragma unroll
            for (int mt = 0; mt < 4; ++mt)
#pragma unroll
                for (int nt = 0; nt < 4; ++nt) mma16816(acc[mt][nt], af[mt], bf[nt]);
        }
        __syncthreads();
        if (c + 2 < NCH) load_stage(c & 1, c + 2);
        asm volatile("cp.async.commit_group;");
    }

#pragma unroll
    for (int nt = 0; nt < 4; ++nt) {
        const int col = bn + wn * 32 + nt * 8 + (lane & 3) * 2;
        const float2 bv = *(const float2*)&bias[col];
#pragma unroll
        for (int mt = 0; mt < 4; ++mt) {
            const int row = bm + wm * 64 + mt * 16 + (lane >> 2);
            float2 v0 = make_float2(acc[mt][nt][0] + bv.x, acc[mt][nt][1] + bv.y);
            float2 v1 = make_float2(acc[mt][nt][2] + bv.x, acc[mt][nt][3] + bv.y);
            *(float2*)&C[(size_t)row * N_LAT + col] = v0;
            *(float2*)&C[(size_t)(row + 8) * N_LAT + col] = v1;
        }
    }
}

// =====================================================================
// topk: candidate superset via 2-level radix bins + fused latents zeroing.
// Suffix scan via warp shuffles (2 barriers/pass instead of 18).
// =====================================================================
__global__ __launch_bounds__(512) void topk_kernel(const float* __restrict__ pre,
                                                   float* __restrict__ latents)
{
    extern __shared__ unsigned su[];           // 16384 keys
    __shared__ unsigned hist[2048];
    __shared__ int wtot[16], wsuf[16];
    __shared__ int s_t1, s_cab, s_b, s_c, s_target;
    __shared__ int s_nhi, s_neq;

    const int row = blockIdx.x;
    const int tid = threadIdx.x;
    const int lane = tid & 31, warp = tid >> 5;
    const float* prow = pre + (size_t)row * N_LAT;
    float* lrow = latents + (size_t)row * N_LAT;

    for (int i = tid; i < 2048; i += 512) hist[i] = 0u;
    if (tid == 0) { s_nhi = 0; s_neq = 0; s_target = NCAND; }
    __syncthreads();

    const float4 z4 = make_float4(0.f, 0.f, 0.f, 0.f);
    for (int i = tid; i < N_LAT / 4; i += 512) {
        float4 v = ((const float4*)prow)[i];
        ((float4*)lrow)[i] = z4;
        unsigned b0 = __float_as_uint(v.x), b1 = __float_as_uint(v.y);
        unsigned b2 = __float_as_uint(v.z), b3 = __float_as_uint(v.w);
        unsigned u0 = (b0 & 0x80000000u) ? ~b0 : (b0 | 0x80000000u);
        unsigned u1 = (b1 & 0x80000000u) ? ~b1 : (b1 | 0x80000000u);
        unsigned u2 = (b2 & 0x80000000u) ? ~b2 : (b2 | 0x80000000u);
        unsigned u3 = (b3 & 0x80000000u) ? ~b3 : (b3 | 0x80000000u);
        *(uint4*)&su[i * 4] = make_uint4(u0, u1, u2, u3);
        atomicAdd(&hist[u0 >> 21], 1u);
        atomicAdd(&hist[u1 >> 21], 1u);
        atomicAdd(&hist[u2 >> 21], 1u);
        atomicAdd(&hist[u3 >> 21], 1u);
    }

    unsigned P = 0;
#pragma unroll
    for (int pass = 0; pass < 2; ++pass) {
        __syncthreads();
        const int target = s_target;
        const int cs = (int)hist[tid * 4] + (int)hist[tid * 4 + 1]
                     + (int)hist[tid * 4 + 2] + (int)hist[tid * 4 + 3];
        // warp-level suffix sum (lane i gets sum of lanes i..31)
        int v = cs;
#pragma unroll
        for (int off = 1; off < 32; off <<= 1) {
            int n = __shfl_down_sync(0xffffffffu, v, off);
            if (lane + off < 32) v += n;
        }
        if (lane == 0) wtot[warp] = v;
        __syncthreads();
        if (warp == 0 && lane < 16) {
            int t = wtot[lane];
#pragma unroll
            for (int off = 1; off < 16; off <<= 1) {
                int n = __shfl_down_sync(0x0000ffffu, t, off);
                if (lane + off < 16) t += n;
            }
            wsuf[lane] = t;
        }
        __syncthreads();
        const int above = (warp < 15) ? wsuf[warp + 1] : 0;
        const int suffix = v + above;          // sum from tid..511
        const int sufnext = suffix - cs;       // sum from tid+1..511
        if (suffix >= target && sufnext < target) { s_t1 = tid; s_cab = sufnext; }
        __syncthreads();
        if (tid == 0) {
            int t1 = s_t1, cum = s_cab, b = 0, c = 0;
            for (int bb = t1 * 4 + 3;; --bb) {
                if (cum + (int)hist[bb] >= target) { b = bb; c = cum; break; }
                cum += (int)hist[bb];
            }
            s_b = b; s_c = c;
        }
        __syncthreads();
        if (pass == 0) {
            const int b1 = s_b;
            const int c1 = s_c;
            if (tid == 0) s_target = NCAND - c1;
            __syncthreads();
            for (int i = tid; i < 2048; i += 512) hist[i] = 0u;
            __syncthreads();
            for (int i = tid; i < N_LAT; i += 512) {
                unsigned u = su[i];
                if ((int)(u >> 21) == b1) atomicAdd(&hist[(u >> 10) & 2047u], 1u);
            }
            P = (unsigned)b1 << 11;
        }
    }
    P |= (unsigned)s_b;
    __syncthreads();

    for (int i = tid; i < N_LAT; i += 512) {
        unsigned hi = su[i] >> 10;
        if (hi > P) {
            int p = atomicAdd(&s_nhi, 1);
            if (p < CAP) g_cand[row * CAP + p] = i;
        } else if (hi == P) {
            int p = atomicAdd(&s_neq, 1);
            if (p < CAP) g_cand[row * CAP + (CAP - 1 - p)] = i;
        }
    }
    __syncthreads();
    if (tid == 0) {
        g_nhi[row] = s_nhi < CAP ? s_nhi : CAP;
        g_neq[row] = s_neq < CAP ? s_neq : CAP;
    }
}

// =====================================================================
// fused refine + recon: compensated-fp32 exact dots, exact top-32,
// latents scatter, then sparse decode — winners never leave smem.
// =====================================================================
__global__ __launch_bounds__(256) void refine_recon_kernel(
    const float* __restrict__ x, const float* __restrict__ We,
    const float* __restrict__ be, const float* __restrict__ b_dec,
    float* __restrict__ latents, float* __restrict__ recon)
{
    __shared__ float4 xs4[D_MODEL / 4];
    __shared__ float cv[CAP];
    __shared__ int   ci[CAP];
    __shared__ int   widx[TOPK];
    __shared__ float wval[TOPK];
    const int row = blockIdx.x;
    const int tid = threadIdx.x;
    const int lane = tid & 31, warp = tid >> 5;

    for (int j = tid; j < D_MODEL / 4; j += 256)
        xs4[j] = ((const float4*)(x + (size_t)row * D_MODEL))[j];
    if (tid < CAP) {
        int nhi = g_nhi[row], neq = g_neq[row];
        bool valid = (tid < nhi) || (tid >= CAP - neq);
        ci[tid] = valid ? g_cand[row * CAP + tid] : -1;
        cv[tid] = -1e30f;
    }
    __syncthreads();

    for (int c = warp; c < CAP; c += 8) {
        const int idx = ci[c];
        if (idx < 0) continue;
        const float4* wr = (const float4*)(We + (size_t)idx * D_MODEL);
        float s = 0.f, e = 0.f;
#pragma unroll
        for (int it = 0; it < D_MODEL / 128; ++it) {   // 6
            float4 w = wr[lane + it * 32];
            float4 a = xs4[lane + it * 32];
            float av[4] = {a.x, a.y, a.z, a.w};
            float wv[4] = {w.x, w.y, w.z, w.w};
#pragma unroll
            for (int q = 0; q < 4; ++q) {
                float p = av[q] * wv[q];
                float pe = fmaf(av[q], wv[q], -p);
                float t = s + p;
                float z = t - s;
                e += ((s - (t - z)) + (p - z)) + pe;
                s = t;
            }
        }
#pragma unroll
        for (int o = 16; o > 0; o >>= 1) {
            float so = __shfl_down_sync(0xffffffffu, s, o);
            float eo = __shfl_down_sync(0xffffffffu, e, o);
            float t = s + so;
            float z = t - s;
            e += ((s - (t - z)) + (so - z)) + eo;
            s = t;
        }
        if (lane == 0) {
            float bb = be[idx];
            float t = s + bb;
            float z = t - s;
            e += (s - (t - z)) + (bb - z);
            cv[c] = t + e;
        }
    }
    __syncthreads();

    // exact rank (ties -> lower index); scatter latents; stage winners
    if (tid < CAP) {
        const int idx = ci[tid];
        if (idx >= 0) {
            const float v = cv[tid];
            int r = 0;
#pragma unroll
            for (int j = 0; j < CAP; ++j) {
                float u = cv[j];
                r += (u > v) || (u == v && ci[j] < idx && ci[j] >= 0);
            }
            if (r < TOPK) {
                float rv = v > 0.f ? v : 0.f;
                latents[(size_t)row * N_LAT + idx] = rv;
                widx[r] = idx;
                wval[r] = rv;
            }
        }
    }
    __syncthreads();

    // sparse decode: recon[row] = sum_k wval[k] * Wt[widx[k]] + b_dec
    float a0 = 0.f, a1 = 0.f, a2 = 0.f;
#pragma unroll 4
    for (int k = 0; k < TOPK; k++) {
        float v = wval[k];
        const float* w = &g_Wt[(size_t)widx[k] * D_MODEL];
        a0 += v * w[tid];
        a1 += v * w[tid + 256];
        a2 += v * w[tid + 512];
    }
    const size_t o = (size_t)row * D_MODEL;
    recon[o + tid]       = a0 + b_dec[tid];
    recon[o + tid + 256] = a1 + b_dec[tid + 256];
    recon[o + tid + 512] = a2 + b_dec[tid + 512];
}

// ---------------- launch (serial, single stream) ----------------
extern "C" void kernel_launch(void* const* d_in, const int* in_sizes, int n_in,
                              void* d_out, int out_size)
{
    const float* x  = (const float*)d_in[0];
    const float* We = (const float*)d_in[1];
    const float* be = (const float*)d_in[2];
    const float* Wd = (const float*)d_in[3];
    const float* bd = (const float*)d_in[4];

    float* out     = (float*)d_out;
    float* latents = out;
    float* recon   = out + (size_t)NROWS * N_LAT;
    float* pre     = recon + (size_t)NROWS * D_MODEL;

    prep_kernel<<<GRID_CX + GRID_CW + GRID_TR, 256>>>(x, We, Wd);

    cudaFuncSetAttribute(gemm_mma, cudaFuncAttributeMaxDynamicSharedMemorySize, GEMM_SMEM);
    gemm_mma<<<dim3(N_LAT / 128, NROWS / 128), 256, GEMM_SMEM>>>(be, pre);

    cudaFuncSetAttribute(topk_kernel, cudaFuncAttributeMaxDynamicSharedMemorySize,
                         N_LAT * (int)sizeof(unsigned));
    topk_kernel<<<NROWS, 512, N_LAT * sizeof(unsigned)>>>(pre, latents);

    refine_recon_kernel<<<NROWS, 256>>>(x, We, be, bd, latents, recon);
}

// round 13
// speedup vs baseline: 1.1049x; 1.0164x over previous
#include <cuda_runtime.h>
#include <cuda_fp16.h>
#include <cstdint>

#define D_MODEL 768
#define N_LAT   16384
#define NROWS   8192
#define TOPK    32
#define NCAND   48
#define CAP     64
#define DELTA   1.5e-3f

// ---------------- device scratch (no allocs allowed) ----------------
__device__ int   g_cand[NROWS * CAP];
__device__ int   g_nhi[NROWS];
__device__ int   g_neq[NROWS];
__device__ float g_Wt[(size_t)N_LAT * D_MODEL];           // W_dec transposed
__device__ __half g_x1[(size_t)NROWS * D_MODEL];          // fp16(x)
__device__ __half g_w1[(size_t)N_LAT * D_MODEL];          // fp16(W_enc)

__device__ __forceinline__ uint32_t smem_u32(const void* p) {
    uint32_t a;
    asm("{ .reg .u64 t; cvta.to.shared.u64 t, %1; cvt.u32.u64 %0, t; }" : "=r"(a) : "l"(p));
    return a;
}

// =====================================================================
// prep: convert x->fp16, W_enc->fp16, transpose W_dec (single launch)
// =====================================================================
#define GRID_CX (NROWS * D_MODEL / 4 / 256)            // 6144
#define GRID_CW (N_LAT * D_MODEL / 4 / 256)            // 49152
#define GRID_TR ((N_LAT / 32) * (D_MODEL / 32))        // 12288

__global__ __launch_bounds__(256) void prep_kernel(
    const float* __restrict__ x, const float* __restrict__ We,
    const float* __restrict__ Wd)
{
    __shared__ float t[32][33];
    const int b = blockIdx.x;
    const int tid = threadIdx.x;

    if (b < GRID_CX) {
        int i = b * 256 + tid;
        float4 v = ((const float4*)x)[i];
        __half2 a = __halves2half2(__float2half_rn(v.x), __float2half_rn(v.y));
        __half2 c = __halves2half2(__float2half_rn(v.z), __float2half_rn(v.w));
        ((uint2*)g_x1)[i] = make_uint2(*(uint32_t*)&a, *(uint32_t*)&c);
    } else if (b < GRID_CX + GRID_CW) {
        int i = (b - GRID_CX) * 256 + tid;
        float4 v = ((const float4*)We)[i];
        __half2 a = __halves2half2(__float2half_rn(v.x), __float2half_rn(v.y));
        __half2 c = __halves2half2(__float2half_rn(v.z), __float2half_rn(v.w));
        ((uint2*)g_w1)[i] = make_uint2(*(uint32_t*)&a, *(uint32_t*)&c);
    } else {
        int tb = b - GRID_CX - GRID_CW;
        const int j0 = (tb & 511) * 32;
        const int d0 = (tb >> 9) * 32;
        const int tx = tid & 31;
        const int ty0 = tid >> 5;
#pragma unroll
        for (int s = 0; s < 32; s += 8) {
            int ty = ty0 + s;
            t[ty][tx] = Wd[(size_t)(d0 + ty) * N_LAT + j0 + tx];
        }
        __syncthreads();
#pragma unroll
        for (int s = 0; s < 32; s += 8) {
            int ty = ty0 + s;
            g_Wt[(size_t)(j0 + ty) * D_MODEL + d0 + tx] = t[tx][ty];
        }
    }
}

// =====================================================================
// GEMM1: pre = x @ W_enc^T + b_enc, fp16 MMA, fp32 accum (round-6 best)
// =====================================================================
#define GBK 64
#define ROWB 144
#define TILEB (128 * ROWB)
#define STAGEB (2 * TILEB)
#define GSTAGES 2
#define GEMM_SMEM (GSTAGES * STAGEB)   // 73728

__device__ __forceinline__ void ldsm4(uint32_t& r0, uint32_t& r1, uint32_t& r2, uint32_t& r3,
                                      uint32_t addr) {
    asm volatile("ldmatrix.sync.aligned.m8n8.x4.shared.b16 {%0,%1,%2,%3}, [%4];"
                 : "=r"(r0), "=r"(r1), "=r"(r2), "=r"(r3) : "r"(addr));
}
__device__ __forceinline__ void mma16816(float* c, const uint32_t* a, const uint32_t* b) {
    asm volatile("mma.sync.aligned.m16n8k16.row.col.f32.f16.f16.f32 "
                 "{%0,%1,%2,%3}, {%4,%5,%6,%7}, {%8,%9}, {%0,%1,%2,%3};"
                 : "+f"(c[0]), "+f"(c[1]), "+f"(c[2]), "+f"(c[3])
                 : "r"(a[0]), "r"(a[1]), "r"(a[2]), "r"(a[3]), "r"(b[0]), "r"(b[1]));
}
__device__ __forceinline__ void cpasync16(uint32_t dst, const void* src) {
    asm volatile("cp.async.cg.shared.global [%0], [%1], 16;" :: "r"(dst), "l"(src));
}

__global__ __launch_bounds__(256, 2) void gemm_mma(
    const float* __restrict__ bias, float* __restrict__ C)
{
    extern __shared__ char sm[];
    const uint32_t sb = smem_u32(sm);
    const int tid = threadIdx.x;
    const int bm = blockIdx.y * 128;
    const int bn = blockIdx.x * 128;
    const int lane = tid & 31;
    const int warp = tid >> 5;
    const int wm = warp & 1;
    const int wn = warp >> 1;

    float acc[4][4][4];
#pragma unroll
    for (int i = 0; i < 4; i++)
#pragma unroll
        for (int j = 0; j < 4; j++)
#pragma unroll
            for (int q = 0; q < 4; q++) acc[i][j][q] = 0.f;

    const __half* ax = g_x1 + (size_t)bm * D_MODEL;
    const __half* bw = g_w1 + (size_t)bn * D_MODEL;

    auto load_stage = [&](int s, int c) {
        const int k0 = c * GBK;
#pragma unroll
        for (int i = 0; i < 8; ++i) {
            int idx = tid + i * 256;
            int t = idx >> 10;
            int rem = idx & 1023;
            int row = rem >> 3, ch = rem & 7;
            uint32_t dst = sb + s * STAGEB + t * TILEB + row * ROWB + ch * 16;
            const __half* base = (t == 0) ? ax : bw;
            cpasync16(dst, base + (size_t)row * D_MODEL + k0 + ch * 8);
        }
    };

    const int NCH = D_MODEL / GBK;   // 12
    load_stage(0, 0);
    asm volatile("cp.async.commit_group;");
    load_stage(1, 1);
    asm volatile("cp.async.commit_group;");

    const uint32_t a_row = (uint32_t)(wm * 64 + (lane & 7) + ((lane >> 3) & 1) * 8);
    const uint32_t a_off = a_row * ROWB + ((lane >> 4) * 16);
    const uint32_t b_row = (uint32_t)(wn * 32 + (lane & 7) + ((lane >> 4) & 1) * 8);
    const uint32_t b_off = b_row * ROWB + (((lane >> 3) & 1) * 16);

    for (int c = 0; c < NCH; ++c) {
        asm volatile("cp.async.wait_group %0;" :: "n"(1));
        __syncthreads();

        const uint32_t stg = sb + (c & 1) * STAGEB;
#pragma unroll
        for (int kg = 0; kg < 4; ++kg) {
            const uint32_t kgo = kg * 32;
            uint32_t af[4][4], bf[4][2];
#pragma unroll
            for (int q = 0; q < 2; ++q)
                ldsm4(bf[2 * q][0], bf[2 * q][1], bf[2 * q + 1][0], bf[2 * q + 1][1],
                      stg + 1 * TILEB + b_off + q * 16 * ROWB + kgo);
#pragma unroll
            for (int mt = 0; mt < 4; ++mt)
                ldsm4(af[mt][0], af[mt][1], af[mt][2], af[mt][3],
                      stg + 0 * TILEB + a_off + mt * 16 * ROWB + kgo);
#pragma unroll
            for (int mt = 0; mt < 4; ++mt)
#pragma unroll
                for (int nt = 0; nt < 4; ++nt) mma16816(acc[mt][nt], af[mt], bf[nt]);
        }
        __syncthreads();
        if (c + 2 < NCH) load_stage(c & 1, c + 2);
        asm volatile("cp.async.commit_group;");
    }

#pragma unroll
    for (int nt = 0; nt < 4; ++nt) {
        const int col = bn + wn * 32 + nt * 8 + (lane & 3) * 2;
        const float2 bv = *(const float2*)&bias[col];
#pragma unroll
        for (int mt = 0; mt < 4; ++mt) {
            const int row = bm + wm * 64 + mt * 16 + (lane >> 2);
            float2 v0 = make_float2(acc[mt][nt][0] + bv.x, acc[mt][nt][1] + bv.y);
            float2 v1 = make_float2(acc[mt][nt][2] + bv.x, acc[mt][nt][3] + bv.y);
            *(float2*)&C[(size_t)row * N_LAT + col] = v0;
            *(float2*)&C[(size_t)(row + 8) * N_LAT + col] = v1;
        }
    }
}

// =====================================================================
// topk: candidate superset via 2-level radix bins + fused latents zeroing.
// =====================================================================
__global__ __launch_bounds__(512) void topk_kernel(const float* __restrict__ pre,
                                                   float* __restrict__ latents)
{
    extern __shared__ unsigned su[];
    __shared__ unsigned hist[2048];
    __shared__ int wtot[16], wsuf[16];
    __shared__ int s_t1, s_cab, s_b, s_c, s_target;
    __shared__ int s_nhi, s_neq;

    const int row = blockIdx.x;
    const int tid = threadIdx.x;
    const int lane = tid & 31, warp = tid >> 5;
    const float* prow = pre + (size_t)row * N_LAT;
    float* lrow = latents + (size_t)row * N_LAT;

    for (int i = tid; i < 2048; i += 512) hist[i] = 0u;
    if (tid == 0) { s_nhi = 0; s_neq = 0; s_target = NCAND; }
    __syncthreads();

    const float4 z4 = make_float4(0.f, 0.f, 0.f, 0.f);
    for (int i = tid; i < N_LAT / 4; i += 512) {
        float4 v = ((const float4*)prow)[i];
        ((float4*)lrow)[i] = z4;
        unsigned b0 = __float_as_uint(v.x), b1 = __float_as_uint(v.y);
        unsigned b2 = __float_as_uint(v.z), b3 = __float_as_uint(v.w);
        unsigned u0 = (b0 & 0x80000000u) ? ~b0 : (b0 | 0x80000000u);
        unsigned u1 = (b1 & 0x80000000u) ? ~b1 : (b1 | 0x80000000u);
        unsigned u2 = (b2 & 0x80000000u) ? ~b2 : (b2 | 0x80000000u);
        unsigned u3 = (b3 & 0x80000000u) ? ~b3 : (b3 | 0x80000000u);
        *(uint4*)&su[i * 4] = make_uint4(u0, u1, u2, u3);
        atomicAdd(&hist[u0 >> 21], 1u);
        atomicAdd(&hist[u1 >> 21], 1u);
        atomicAdd(&hist[u2 >> 21], 1u);
        atomicAdd(&hist[u3 >> 21], 1u);
    }

    unsigned P = 0;
#pragma unroll
    for (int pass = 0; pass < 2; ++pass) {
        __syncthreads();
        const int target = s_target;
        const int cs = (int)hist[tid * 4] + (int)hist[tid * 4 + 1]
                     + (int)hist[tid * 4 + 2] + (int)hist[tid * 4 + 3];
        int v = cs;
#pragma unroll
        for (int off = 1; off < 32; off <<= 1) {
            int n = __shfl_down_sync(0xffffffffu, v, off);
            if (lane + off < 32) v += n;
        }
        if (lane == 0) wtot[warp] = v;
        __syncthreads();
        if (warp == 0 && lane < 16) {
            int t = wtot[lane];
#pragma unroll
            for (int off = 1; off < 16; off <<= 1) {
                int n = __shfl_down_sync(0x0000ffffu, t, off);
                if (lane + off < 16) t += n;
            }
            wsuf[lane] = t;
        }
        __syncthreads();
        const int above = (warp < 15) ? wsuf[warp + 1] : 0;
        const int suffix = v + above;
        const int sufnext = suffix - cs;
        if (suffix >= target && sufnext < target) { s_t1 = tid; s_cab = sufnext; }
        __syncthreads();
        if (tid == 0) {
            int t1 = s_t1, cum = s_cab, b = 0, c = 0;
            for (int bb = t1 * 4 + 3;; --bb) {
                if (cum + (int)hist[bb] >= target) { b = bb; c = cum; break; }
                cum += (int)hist[bb];
            }
            s_b = b; s_c = c;
        }
        __syncthreads();
        if (pass == 0) {
            const int b1 = s_b;
            const int c1 = s_c;
            if (tid == 0) s_target = NCAND - c1;
            __syncthreads();
            for (int i = tid; i < 2048; i += 512) hist[i] = 0u;
            __syncthreads();
            for (int i = tid; i < N_LAT; i += 512) {
                unsigned u = su[i];
                if ((int)(u >> 21) == b1) atomicAdd(&hist[(u >> 10) & 2047u], 1u);
            }
            P = (unsigned)b1 << 11;
        }
    }
    P |= (unsigned)s_b;
    __syncthreads();

    for (int i = tid; i < N_LAT; i += 512) {
        unsigned hi = su[i] >> 10;
        if (hi > P) {
            int p = atomicAdd(&s_nhi, 1);
            if (p < CAP) g_cand[row * CAP + p] = i;
        } else if (hi == P) {
            int p = atomicAdd(&s_neq, 1);
            if (p < CAP) g_cand[row * CAP + (CAP - 1 - p)] = i;
        }
    }
    __syncthreads();
    if (tid == 0) {
        g_nhi[row] = s_nhi < CAP ? s_nhi : CAP;
        g_neq[row] = s_neq < CAP ? s_neq : CAP;
    }
}

// =====================================================================
// fused refine + recon with BAND refinement:
// rank candidates by approx pre; exact (compensated-fp32) dots only for
// candidates within +-DELTA of the approx 32nd value; then exact top-32
// membership, latents scatter, sparse decode.
// =====================================================================
__global__ __launch_bounds__(256) void refine_recon_kernel(
    const float* __restrict__ x, const float* __restrict__ We,
    const float* __restrict__ be, const float* __restrict__ b_dec,
    const float* __restrict__ pre,
    float* __restrict__ latents, float* __restrict__ recon)
{
    __shared__ float4 xs4[D_MODEL / 4];
    __shared__ float kv[CAP];      // mixed keys (approx, band->exact)
    __shared__ int   ci[CAP];
    __shared__ int   band[CAP];    // indices into ci of band members
    __shared__ int   s_nband;
    __shared__ float s_v32;
    __shared__ int   widx[TOPK];
    __shared__ float wval[TOPK];
    const int row = blockIdx.x;
    const int tid = threadIdx.x;
    const int lane = tid & 31, warp = tid >> 5;

    for (int j = tid; j < D_MODEL / 4; j += 256)
        xs4[j] = ((const float4*)(x + (size_t)row * D_MODEL))[j];
    if (tid == 0) s_nband = 0;
    if (tid < CAP) {
        int nhi = g_nhi[row], neq = g_neq[row];
        bool valid = (tid < nhi) || (tid >= CAP - neq);
        int idx = valid ? g_cand[row * CAP + tid] : -1;
        ci[tid] = idx;
        kv[tid] = (idx >= 0) ? pre[(size_t)row * N_LAT + idx] : -1e30f;
    }
    __syncthreads();

    // approx rank -> find v32 (ties by lower index)
    if (tid < CAP) {
        const int idx = ci[tid];
        if (idx >= 0) {
            const float v = kv[tid];
            int r = 0;
#pragma unroll
            for (int j = 0; j < CAP; ++j) {
                float u = kv[j];
                r += (u > v) || (u == v && ci[j] < idx && ci[j] >= 0);
            }
            if (r == TOPK - 1) s_v32 = v;
        }
    }
    __syncthreads();
    const float v32 = s_v32;

    // band membership
    if (tid < CAP) {
        if (ci[tid] >= 0 && fabsf(kv[tid] - v32) <= DELTA) {
            int p = atomicAdd(&s_nband, 1);
            band[p] = tid;
        }
    }
    __syncthreads();
    const int nband = s_nband;

    // exact compensated-fp32 dots for band members only
    for (int c = warp; c < nband; c += 8) {
        const int slot = band[c];
        const int idx = ci[slot];
        const float4* wr = (const float4*)(We + (size_t)idx * D_MODEL);
        float s = 0.f, e = 0.f;
#pragma unroll
        for (int it = 0; it < D_MODEL / 128; ++it) {
            float4 w = wr[lane + it * 32];
            float4 a = xs4[lane + it * 32];
            float av[4] = {a.x, a.y, a.z, a.w};
            float wv[4] = {w.x, w.y, w.z, w.w};
#pragma unroll
            for (int q = 0; q < 4; ++q) {
                float p = av[q] * wv[q];
                float pe = fmaf(av[q], wv[q], -p);
                float t = s + p;
                float z = t - s;
                e += ((s - (t - z)) + (p - z)) + pe;
                s = t;
            }
        }
#pragma unroll
        for (int o = 16; o > 0; o >>= 1) {
            float so = __shfl_down_sync(0xffffffffu, s, o);
            float eo = __shfl_down_sync(0xffffffffu, e, o);
            float t = s + so;
            float z = t - s;
            e += ((s - (t - z)) + (so - z)) + eo;
            s = t;
        }
        if (lane == 0) {
            float bb = be[idx];
            float t = s + bb;
            float z = t - s;
            e += (s - (t - z)) + (bb - z);
            kv[slot] = t + e;
        }
    }
    __syncthreads();

    // final rank on mixed keys; scatter latents; stage winners
    if (tid < CAP) {
        const int idx = ci[tid];
        if (idx >= 0) {
            const float v = kv[tid];
            int r = 0;
#pragma unroll
            for (int j = 0; j < CAP; ++j) {
                float u = kv[j];
                r += (u > v) || (u == v && ci[j] < idx && ci[j] >= 0);
            }
            if (r < TOPK) {
                float rv = v > 0.f ? v : 0.f;
                latents[(size_t)row * N_LAT + idx] = rv;
                widx[r] = idx;
                wval[r] = rv;
            }
        }
    }
    __syncthreads();

    // sparse decode: recon[row] = sum_k wval[k] * Wt[widx[k]] + b_dec
    float a0 = 0.f, a1 = 0.f, a2 = 0.f;
#pragma unroll 4
    for (int k = 0; k < TOPK; k++) {
        float v = wval[k];
        const float* w = &g_Wt[(size_t)widx[k] * D_MODEL];
        a0 += v * w[tid];
        a1 += v * w[tid + 256];
        a2 += v * w[tid + 512];
    }
    const size_t o = (size_t)row * D_MODEL;
    recon[o + tid]       = a0 + b_dec[tid];
    recon[o + tid + 256] = a1 + b_dec[tid + 256];
    recon[o + tid + 512] = a2 + b_dec[tid + 512];
}

// ---------------- launch (serial, single stream) ----------------
extern "C" void kernel_launch(void* const* d_in, const int* in_sizes, int n_in,
                              void* d_out, int out_size)
{
    const float* x  = (const float*)d_in[0];
    const float* We = (const float*)d_in[1];
    const float* be = (const float*)d_in[2];
    const float* Wd = (const float*)d_in[3];
    const float* bd = (const float*)d_in[4];

    float* out     = (float*)d_out;
    float* latents = out;
    float* recon   = out + (size_t)NROWS * N_LAT;
    float* pre     = recon + (size_t)NROWS * D_MODEL;

    prep_kernel<<<GRID_CX + GRID_CW + GRID_TR, 256>>>(x, We, Wd);

    cudaFuncSetAttribute(gemm_mma, cudaFuncAttributeMaxDynamicSharedMemorySize, GEMM_SMEM);
    gemm_mma<<<dim3(N_LAT / 128, NROWS / 128), 256, GEMM_SMEM>>>(be, pre);

    cudaFuncSetAttribute(topk_kernel, cudaFuncAttributeMaxDynamicSharedMemorySize,
                         N_LAT * (int)sizeof(unsigned));
    topk_kernel<<<NROWS, 512, N_LAT * sizeof(unsigned)>>>(pre, latents);

    refine_recon_kernel<<<NROWS, 256>>>(x, We, be, bd, pre, latents, recon);
}